// round 17
// baseline (speedup 1.0000x reference)
#include <cuda_runtime.h>
#include <math.h>

#define BB 8
#define LL 48000
#define VV 28
#define QQ 256
#define CC 256
#define TT 960          // L / 50
#define NGD 29          // V + 1

#define ENC_BLOCKS 120          // 8 b * 15 chunks of 64 t
#define TR_BLOCKS  256
#define TR_END     (ENC_BLOCKS + TR_BLOCKS)    // 376
#define TBL_BLOCKS 290          // 29 i x 10 j
#define TBL_END    (TR_END + TBL_BLOCKS)       // 666
#define LOSS_BLK   148
#define GRID1      (TBL_END + LOSS_BLK)        // 814

// ---------------- scratch ----------------
__device__ int    g_preds[BB * TT];
__device__ float  g_Wd2T[10 * 256 * 256];     // [j][c][q]
__device__ float  g_M[NGD * 5 * 10 * 256];    // logprob table: acc + bd2 - LSE
__device__ double g_prec[LOSS_BLK];
__device__ double g_pkl[LOSS_BLK];
__device__ int    g_ticket;                   // all zero-init; reset by final block
__device__ int    g_trdone;
__device__ int    g_encdone;
__device__ int    g_tbldone;

// ---------------- f32x2 helpers ----------------
__device__ __forceinline__ void fma2(unsigned long long& d, unsigned long long a,
                                     unsigned long long b, unsigned long long c) {
    asm("fma.rn.f32x2 %0, %1, %2, %3;" : "=l"(d) : "l"(a), "l"(b), "l"(c));
}
__device__ __forceinline__ void add2(unsigned long long& d, unsigned long long a,
                                     unsigned long long b) {
    asm("add.rn.f32x2 %0, %1, %2;" : "=l"(d) : "l"(a), "l"(b));
}
__device__ __forceinline__ unsigned long long bcast2(float v) {
    unsigned long long r;
    asm("mov.b64 %0, {%1, %1};" : "=l"(r) : "f"(v));
    return r;
}
__device__ __forceinline__ void unpack2(unsigned long long v, float& lo, float& hi) {
    asm("mov.b64 {%0, %1}, %2;" : "=f"(lo), "=f"(hi) : "l"(v));
}

// ---------------- encoder smem layout (quarter-split, proven) ----------------
#define W2STRIDE 164
#define W1STRIDE 14
#define ENC_T    64
#define LSTRIDE  33
#define W2S_OFF 0
#define W1S_OFF (256 * W2STRIDE)
#define XS_OFF  (W1S_OFF + 256 * W1STRIDE)
#define B1S_OFF (XS_OFF + ENC_T * 50)
#define B2S_OFF (B1S_OFF + 256)
#define LS_OFF  (B2S_OFF + 32)
#define ENC_SMEM_FLOATS (LS_OFF + ENC_T * LSTRIDE)
#define ENC_SMEM_BYTES  (ENC_SMEM_FLOATS * 4)       // ~204.7 KB

// ---------------- single fused kernel: encoder + transpose + table + loss ----------------
__global__ __launch_bounds__(512, 1)
void k_all(const float* __restrict__ x, const int* __restrict__ x_sl,
           const float* __restrict__ ngrams, const float* __restrict__ gumbel,
           const float* __restrict__ W1, const float* __restrict__ b1,
           const float* __restrict__ W2, const float* __restrict__ b2,
           const float* __restrict__ Wd1, const float* __restrict__ bd1,
           const float* __restrict__ Wd2, const float* __restrict__ bd2,
           float* __restrict__ out)
{
    extern __shared__ float sm[];
    const int tid = threadIdx.x;

    if (blockIdx.x >= TBL_END) {
        // ===== loss branch: spins on encoder+table, then grid-strided gather =====
        const int lb = blockIdx.x - TBL_END;        // 0..147
        double* srd  = (double*)sm;                 // 16
        double* skd  = (double*)sm + 16;            // 16
        int*    flag = (int*)((double*)sm + 32);

        if (tid == 0)
            while (*(volatile int*)&g_encdone < ENC_BLOCKS ||
                   *(volatile int*)&g_tbldone < TBL_BLOCKS) __nanosleep(64);
        __syncthreads();

        float rec = 0.f, kl = 0.f;
        for (int gid = lb * 512 + tid; gid < BB * LL; gid += LOSS_BLK * 512) {
            const int b   = gid / LL, l = gid % LL;
            const int sl  = x_sl[b];
            const int zsl = sl / 50;
            const int t   = l / 50;
            if (l < sl) {
                const float xv = x[gid];
                float y = log1pf(255.f * fabsf(xv)) / 5.5451774444795625f;
                y = copysignf(y, xv);
                int tq = (int)floorf((y + 1.0f) * 0.5f * 256.0f);
                tq = min(max(tq, 0), 255);
                const int j2 = (l / 10) % 5;
                const int j  = l % 10;
                const int i  = (t < zsl) ? __ldcg(&g_preds[b * TT + t]) : 28;
                rec -= __ldcg(&g_M[(((i * 5 + j2) * 10 + j) * 256) + tq]);
            }
            if ((l % 50) == 0 && t < zsl) {
                const int p  = __ldcg(&g_preds[b * TT + t]);
                const int a0 = (t >= 2) ? __ldcg(&g_preds[b * TT + t - 2]) : 28;
                const int a1 = (t >= 1) ? __ldcg(&g_preds[b * TT + t - 1]) : 28;
                const float pr = ngrams[(a0 * 29 + a1) * 28 + p];
                kl += logf(1.0f / (pr + 1e-10f) + 1e-10f);
            }
        }

        const int lane = tid & 31, wid = tid >> 5;
        for (int s = 16; s > 0; s >>= 1) {
            rec += __shfl_down_sync(0xffffffffu, rec, s);
            kl  += __shfl_down_sync(0xffffffffu, kl,  s);
        }
        if (lane == 0) { srd[wid] = (double)rec; skd[wid] = (double)kl; }
        __syncthreads();
        if (tid == 0) {
            double r = 0.0, k = 0.0;
#pragma unroll
            for (int w2 = 0; w2 < 16; w2++) { r += srd[w2]; k += skd[w2]; }
            g_prec[lb] = r;
            g_pkl[lb]  = k;
            __threadfence();
            int tck = atomicAdd(&g_ticket, 1);
            *flag = (tck == LOSS_BLK - 1);
        }
        __syncthreads();

        if (*flag) {
            double r = 0.0, k = 0.0;
            for (int i = tid; i < LOSS_BLK; i += 512) {
                r += __ldcg(&g_prec[i]);
                k += __ldcg(&g_pkl[i]);
            }
            for (int s = 16; s > 0; s >>= 1) {
                r += __shfl_down_sync(0xffffffffu, r, s);
                k += __shfl_down_sync(0xffffffffu, k, s);
            }
            __syncthreads();
            if (lane == 0) { srd[wid] = r; skd[wid] = k; }
            __syncthreads();
            if (tid == 0) {
                double R = 0.0, K = 0.0;
#pragma unroll
                for (int w2 = 0; w2 < 16; w2++) { R += srd[w2]; K += skd[w2]; }
                long long sx = 0, sz = 0;
#pragma unroll
                for (int bb = 0; bb < BB; bb++) { sx += x_sl[bb]; sz += x_sl[bb] / 50; }
                out[0] = (float)(R / (double)sx + K / (double)sz);
                g_ticket  = 0;          // self-reset for next replay
                g_trdone  = 0;
                g_encdone = 0;
                g_tbldone = 0;
            }
        }
        return;
    }

    if (blockIdx.x >= TR_END) {
        // ===== table branch: one (i,j); waits for transpose, c split over halves =====
        const int bi = blockIdx.x - TR_END;
        const int i = bi / 10, j = bi % 10;
        float* rv   = sm;            // 1280
        float* part = sm + 1280;     // 1280
        float* red  = sm + 2560;     // 8

        if (tid == 0)
            while (*(volatile int*)&g_trdone < TR_BLOCKS) __nanosleep(64);
        __syncthreads();

        for (int lin = tid; lin < 1280; lin += 512) {
            int c = lin / 5, j2 = lin % 5;
            float w = (i < VV) ? Wd1[i * 1280 + lin] : 0.f;
            rv[j2 * 256 + c] = fminf(fmaxf(w + bd1[c], 0.f), 6.f);
        }
        __syncthreads();

        const int half = tid >> 8;
        const int q    = tid & 255;
        float acc[5] = {0.f, 0.f, 0.f, 0.f, 0.f};
        const float* wt = g_Wd2T + j * 65536 + half * (128 * 256) + q;
#pragma unroll 16
        for (int c = 0; c < 128; c++) {
            float w = __ldcg(wt + c * 256);
#pragma unroll
            for (int j2 = 0; j2 < 5; j2++)
                acc[j2] += rv[j2 * 256 + half * 128 + c] * w;
        }
        if (half) {
#pragma unroll
            for (int j2 = 0; j2 < 5; j2++) part[j2 * 256 + q] = acc[j2];
        }
        __syncthreads();
        if (!half) {
#pragma unroll
            for (int j2 = 0; j2 < 5; j2++) acc[j2] += part[j2 * 256 + q];
        }

        const float bdq  = bd2[q];
        const int   lane = tid & 31, wid = tid >> 5;
        for (int j2 = 0; j2 < 5; j2++) {
            float v = 0.f;
            if (!half) {
                v = acc[j2] + bdq;
                float m = v;
                for (int s = 16; s > 0; s >>= 1)
                    m = fmaxf(m, __shfl_xor_sync(0xffffffffu, m, s));
                if (lane == 0) red[wid] = m;
            }
            __syncthreads();
            float mAll = red[0];
#pragma unroll
            for (int w2 = 1; w2 < 8; w2++) mAll = fmaxf(mAll, red[w2]);
            __syncthreads();
            if (!half) {
                float e = expf(v - mAll);
                for (int s = 16; s > 0; s >>= 1)
                    e += __shfl_xor_sync(0xffffffffu, e, s);
                if (lane == 0) red[wid] = e;
            }
            __syncthreads();
            if (!half) {
                float ssum = 0.f;
#pragma unroll
                for (int w2 = 0; w2 < 8; w2++) ssum += red[w2];
                g_M[((i * 5 + j2) * 10 + j) * 256 + q] = v - (mAll + logf(ssum));
            }
            __syncthreads();
        }
        __threadfence();
        __syncthreads();
        if (tid == 0) atomicAdd(&g_tbldone, 1);
        return;
    }

    if (blockIdx.x >= ENC_BLOCKS) {
        // ===== transpose branch =====
        const int c = blockIdx.x - ENC_BLOCKS;
        float* tile = sm;
        for (int lin = tid; lin < 2560; lin += 512)
            tile[lin] = Wd2[c * 2560 + lin];
        __syncthreads();
        if (tid < 256) {
            const int q = tid;
#pragma unroll
            for (int j = 0; j < 10; j++)
                g_Wd2T[j * 65536 + c * 256 + q] = tile[q * 10 + j];
        }
        __threadfence();
        __syncthreads();
        if (tid == 0) atomicAdd(&g_trdone, 1);
        return;
    }

    // ===== encoder branch (quarter-split, proven) =====
    float* W2s = sm + W2S_OFF;
    float* W1s = sm + W1S_OFF;
    float* xs  = sm + XS_OFF;
    float* b1s = sm + B1S_OFF;
    float* b2s = sm + B2S_OFF;
    float* ls  = sm + LS_OFF;

    const int b   = blockIdx.x / 15;
    const int t0  = (blockIdx.x % 15) * ENC_T;

    for (int lin = tid; lin < 28 * 256 * 5; lin += 512) {
        int o = lin / 1280, rem = lin % 1280;
        int c = rem / 5,    kk  = rem % 5;
        int qd = o >> 3, oo = o & 7;
        W2s[c * W2STRIDE + qd * 40 + kk * 8 + oo] = W2[lin];
    }
    for (int lin = tid; lin < 256 * 5 * 4; lin += 512) {
        int c = lin / 20, kk = (lin % 20) / 4, oo = (lin % 4) + 4;
        W2s[c * W2STRIDE + 120 + kk * 8 + oo] = 0.f;
    }
    for (int lin = tid; lin < 2560; lin += 512)
        W1s[(lin / 10) * W1STRIDE + (lin % 10)] = W1[lin];
    for (int lin = tid; lin < ENC_T * 50; lin += 512)
        xs[lin] = x[b * LL + t0 * 50 + lin];
    if (tid < 256) b1s[tid] = b1[tid];
    if (tid < 28)  b2s[tid] = b2[tid];
    __syncthreads();

    const int s   = tid >> 3;
    const int cg  = tid & 7;
    const int oq  = s & 3;

    const unsigned long long* xsp = (const unsigned long long*)(xs + 50 * s);
    unsigned long long xr2[25];
#pragma unroll
    for (int j = 0; j < 25; j++) xr2[j] = xsp[j];

    unsigned long long acc[4][4];
#pragma unroll
    for (int r = 0; r < 4; r++)
#pragma unroll
        for (int u = 0; u < 4; u++) acc[r][u] = 0ULL;

    for (int ci = 0; ci < 32; ci++) {
        const int c = cg + 8 * ci;
        const unsigned long long* w1p = (const unsigned long long*)(W1s + c * W1STRIDE);
        const float b1c = b1s[c];
        const float* wq = W2s + c * W2STRIDE + oq * 40;

#pragma unroll
        for (int kk = 0; kk < 5; kk++) {
            unsigned long long s2 = 0ULL;
#pragma unroll
            for (int k2 = 0; k2 < 5; k2++)
                fma2(s2, xr2[kk * 5 + k2], w1p[k2], s2);
            float lo, hi; unpack2(s2, lo, hi);
            const float h0 = fminf(fmaxf(lo + hi + b1c, 0.f), 6.f);
            const float h1 = __shfl_xor_sync(0xffffffffu, h0, 8);
            const float h2 = __shfl_xor_sync(0xffffffffu, h0, 16);
            const float h3 = __shfl_xor_sync(0xffffffffu, h1, 16);

            const ulonglong2* wp = (const ulonglong2*)(wq + kk * 8);
            const ulonglong2 w01 = wp[0];
            const ulonglong2 w23 = wp[1];

            const unsigned long long hp0 = bcast2(h0);
            const unsigned long long hp1 = bcast2(h1);
            const unsigned long long hp2 = bcast2(h2);
            const unsigned long long hp3 = bcast2(h3);

            fma2(acc[0][0], hp0, w01.x, acc[0][0]);
            fma2(acc[0][1], hp0, w01.y, acc[0][1]);
            fma2(acc[0][2], hp0, w23.x, acc[0][2]);
            fma2(acc[0][3], hp0, w23.y, acc[0][3]);
            fma2(acc[1][0], hp1, w01.x, acc[1][0]);
            fma2(acc[1][1], hp1, w01.y, acc[1][1]);
            fma2(acc[1][2], hp1, w23.x, acc[1][2]);
            fma2(acc[1][3], hp1, w23.y, acc[1][3]);
            fma2(acc[2][0], hp2, w01.x, acc[2][0]);
            fma2(acc[2][1], hp2, w01.y, acc[2][1]);
            fma2(acc[2][2], hp2, w23.x, acc[2][2]);
            fma2(acc[2][3], hp2, w23.y, acc[2][3]);
            fma2(acc[3][0], hp3, w01.x, acc[3][0]);
            fma2(acc[3][1], hp3, w01.y, acc[3][1]);
            fma2(acc[3][2], hp3, w23.x, acc[3][2]);
            fma2(acc[3][3], hp3, w23.y, acc[3][3]);
        }
    }

#pragma unroll
    for (int r = 0; r < 4; r++)
#pragma unroll
        for (int u = 0; u < 4; u++) {
            unsigned long long v = acc[r][u], o2;
            o2 = __shfl_xor_sync(0xffffffffu, v, 1); add2(v, v, o2);
            o2 = __shfl_xor_sync(0xffffffffu, v, 2); add2(v, v, o2);
            o2 = __shfl_xor_sync(0xffffffffu, v, 4); add2(v, v, o2);
            acc[r][u] = v;
        }

    if (cg == 0) {
        const int sbase = s & ~3;
#pragma unroll
        for (int r = 0; r < 4; r++) {
            const int tloc = sbase + ((s & 3) ^ r);
            float* lrow = ls + tloc * LSTRIDE + oq * 8;
#pragma unroll
            for (int u = 0; u < 4; u++) {
                float lo, hi; unpack2(acc[r][u], lo, hi);
                lrow[2 * u]     = lo;
                lrow[2 * u + 1] = hi;
            }
        }
    }
    __syncthreads();

    if (tid < ENC_T) {
        const int tg = t0 + tid;
        const float* g = gumbel + (b * TT + tg) * VV;
        const float* lrow = ls + tid * LSTRIDE;
        float best = -1e30f; int bi2 = 0;
#pragma unroll
        for (int o = 0; o < 28; o++) {
            float v = lrow[o] + b2s[o] + g[o];
            if (v > best) { best = v; bi2 = o; }
        }
        g_preds[b * TT + tg] = bi2;
    }
    __threadfence();
    __syncthreads();
    if (tid == 0) atomicAdd(&g_encdone, 1);
}

// ---------------- launch: ONE kernel, zero graph gaps ----------------
extern "C" void kernel_launch(void* const* d_in, const int* in_sizes, int n_in,
                              void* d_out, int out_size)
{
    const float* x      = (const float*)d_in[0];
    const int*   x_sl   = (const int*)  d_in[1];
    const float* ngrams = (const float*)d_in[4];
    const float* gumbel = (const float*)d_in[5];
    const float* W1     = (const float*)d_in[6];
    const float* b1     = (const float*)d_in[7];
    const float* W2     = (const float*)d_in[8];
    const float* b2     = (const float*)d_in[9];
    const float* Wd1    = (const float*)d_in[10];
    const float* bd1    = (const float*)d_in[11];
    const float* Wd2    = (const float*)d_in[12];
    const float* bd2    = (const float*)d_in[13];
    float* out = (float*)d_out;

    cudaFuncSetAttribute(k_all, cudaFuncAttributeMaxDynamicSharedMemorySize,
                         ENC_SMEM_BYTES);

    k_all<<<GRID1, 512, ENC_SMEM_BYTES>>>(
        x, x_sl, ngrams, gumbel, W1, b1, W2, b2, Wd1, bd1, Wd2, bd2, out);
}